// round 16
// baseline (speedup 1.0000x reference)
#include <cuda_runtime.h>
#include <cuda_fp16.h>
#include <cstdint>

#define F 128
#define M 2
#define ROW 1024                 // STRIDE*F*M floats per output row
#define SEGS_PER_BIN 8           // 8 rows; tile = 4096 half2 = 16KB; bin = seg >> 3
#define NBINS 8192               // covers 65536 segments
#define NBLK 296                 // 2 count blocks per SM
#define PBLK 148                 // 1 place block per SM (32KB s_off)
#define EMAX 4200448             // max events (E=4194304 + slack)
#define DT_SCALE 524287.0f       // 2^19 - 1

// Static scratch. g_sorted packed 4B/event: 16.8MB -> L2-resident after place.
__device__ unsigned g_sorted[EMAX];
__device__ unsigned g_counts[(size_t)NBLK * NBINS];
__device__ unsigned g_offs[(size_t)NBLK * NBINS];
__device__ unsigned g_totals[NBINS];
__device__ unsigned g_base[NBINS];

// ---------------------------------------------------------------------------
// Pass 1: per-block histogram of bins (smem atomics only), coalesced dump.
// 2 blocks/SM; reads ONLY the segment array (16MB).
// ---------------------------------------------------------------------------
__global__ void __launch_bounds__(1024, 2) count_kernel(
    const int4* __restrict__ seg4, int n4,
    const int*  __restrict__ seg_s, int n_events, int chunk)
{
    __shared__ unsigned cnt[NBINS];   // 32KB
    int t = threadIdx.x;
    for (int i = t; i < NBINS; i += 1024) cnt[i] = 0;
    __syncthreads();

    int start = blockIdx.x * chunk;
    int end   = start + chunk; if (end > n4) end = n4;
    for (int i = start + t; i < end; i += 1024) {
        int4 a = __ldcs(&seg4[i]);
        atomicAdd(&cnt[(unsigned)a.x >> 3], 1u);
        atomicAdd(&cnt[(unsigned)a.y >> 3], 1u);
        atomicAdd(&cnt[(unsigned)a.z >> 3], 1u);
        atomicAdd(&cnt[(unsigned)a.w >> 3], 1u);
    }
    int rem = n_events & 3;
    if (blockIdx.x == 0 && t < rem)
        atomicAdd(&cnt[(unsigned)seg_s[n4 * 4 + t] >> 3], 1u);
    __syncthreads();

    unsigned* dst = g_counts + (size_t)blockIdx.x * NBINS;
    for (int i = t; i < NBINS; i += 1024) dst[i] = cnt[i];
}

// ---------------------------------------------------------------------------
// Pass 2a: per-bin serial scan across count blocks. Place uses PBLK block
// offsets: place block b covers count chunks {b, b+PBLK} merged.
// Layout: g_offs[b*NBINS + i] = prefix for count-block b.
// ---------------------------------------------------------------------------
__global__ void scan_blocks_kernel() {
    int i = blockIdx.x * blockDim.x + threadIdx.x;
    if (i >= NBINS) return;
    unsigned run = 0;
    #pragma unroll 8
    for (int b = 0; b < NBLK; b++) {
        unsigned c = g_counts[(size_t)b * NBINS + i];
        g_offs[(size_t)b * NBINS + i] = run;
        run += c;
    }
    g_totals[i] = run;
}

// ---------------------------------------------------------------------------
// Pass 2b: exclusive scan of the 8192 bin totals (single block).
// ---------------------------------------------------------------------------
__global__ void __launch_bounds__(1024) base_scan_kernel() {
    __shared__ unsigned s[1024];
    int t = threadIdx.x;
    unsigned loc[8], v = 0;
    #pragma unroll
    for (int j = 0; j < 8; j++) { loc[j] = g_totals[t * 8 + j]; v += loc[j]; }
    s[t] = v;
    __syncthreads();
    for (int off = 1; off < 1024; off <<= 1) {
        unsigned x = (t >= off) ? s[t - off] : 0u;
        __syncthreads();
        s[t] += x;
        __syncthreads();
    }
    unsigned run = s[t] - v;   // exclusive prefix
    #pragma unroll
    for (int j = 0; j < 8; j++) { g_base[t * 8 + j] = run; run += loc[j]; }
}

// ---------------------------------------------------------------------------
// Pass 3: single full-range place (4-event body; structural floor ~37us).
// Place block p handles count-chunk p only (grid = NBLK so chunks match the
// count pass 1:1). Positions via smem atomicAdd on per-chunk offsets.
// ---------------------------------------------------------------------------
__global__ void __launch_bounds__(1024) place_kernel(
    const float4* __restrict__ dt4,
    const int4*   __restrict__ id4,
    const int4*   __restrict__ seg4,
    int n4,
    const float* __restrict__ dt_s,
    const int*   __restrict__ id_s,
    const int*   __restrict__ seg_s,
    int n_events, int chunk)
{
    __shared__ unsigned s_off[NBINS];   // 32KB
    int t = threadIdx.x;
    const unsigned* offs = g_offs + (size_t)blockIdx.x * NBINS;
    for (int i = t; i < NBINS; i += 1024) s_off[i] = g_base[i] + offs[i];
    __syncthreads();

    int start = blockIdx.x * chunk;
    int end   = start + chunk; if (end > n4) end = n4;
    for (int i = start + t; i < end; i += 1024) {
        float4 d  = __ldcs(&dt4[i]);
        int4   id = __ldcs(&id4[i]);
        int4   sg = __ldcs(&seg4[i]);
        float dts[4] = {d.x, d.y, d.z, d.w};
        int   ids[4] = {id.x, id.y, id.z, id.w};
        int   sgs[4] = {sg.x, sg.y, sg.z, sg.w};
        #pragma unroll
        for (int k = 0; k < 4; k++) {
            unsigned bin = (unsigned)sgs[k] >> 3;
            unsigned pos = atomicAdd(&s_off[bin], 1u);
            unsigned lc  = (((unsigned)sgs[k] & 7u) << 10) | ((unsigned)ids[k] << 1);
            float dq = fminf(fmaxf(dts[k], 0.f), 1.f);
            unsigned q = (unsigned)__fmaf_rn(dq, DT_SCALE, 0.5f);
            if (q > 524287u) q = 524287u;
            g_sorted[pos] = (lc << 19) | q;
        }
    }
    int rem = n_events & 3;
    if (blockIdx.x == 0 && t < rem) {
        int e = n4 * 4 + t;
        unsigned bin = (unsigned)seg_s[e] >> 3;
        unsigned pos = atomicAdd(&s_off[bin], 1u);
        unsigned lc  = (((unsigned)seg_s[e] & 7u) << 10) | ((unsigned)id_s[e] << 1);
        float dq = fminf(fmaxf(dt_s[e], 0.f), 1.f);
        unsigned q = (unsigned)__fmaf_rn(dq, DT_SCALE, 0.5f);
        if (q > 524287u) q = 524287u;
        g_sorted[pos] = (lc << 19) | q;
    }
}

// ---------------------------------------------------------------------------
// Pass 4: one 512-thread block per bin; events contiguous + L2-resident.
// Accumulate in a 16KB half2 tile (ONE smem atomic per event), convert to
// fp32 on the sequential streamed store-out. 4 blocks/SM (2048 threads).
// ---------------------------------------------------------------------------
__global__ void __launch_bounds__(512) gather_kernel(
    const float* __restrict__ decay,   // [F*M]
    float* __restrict__ out,
    long long n_out)
{
    __shared__ __half2 acc[SEGS_PER_BIN * ROW / 2];   // 16KB; index = loc>>1
    __shared__ float2  rate2[F];

    int t = threadIdx.x;
    uint2* accz = (uint2*)acc;                         // 2048 x 8B
    #pragma unroll
    for (int j = 0; j < 2048 / 512; j++)
        accz[j * 512 + t] = make_uint2(0u, 0u);
    if (t < F) {
        float x0 = decay[t * M + 0];
        float x1 = decay[t * M + 1];
        rate2[t].x = fmaxf(x0, 0.f) + log1pf(expf(-fabsf(x0)));
        rate2[t].y = fmaxf(x1, 0.f) + log1pf(expf(-fabsf(x1)));
    }
    __syncthreads();

    unsigned bin   = blockIdx.x;
    unsigned start = g_base[bin];
    unsigned cnt   = g_totals[bin];

    for (unsigned e = start + t; e < start + cnt; e += 512) {
        unsigned word = g_sorted[e];
        unsigned loc  = word >> 19;
        float    dtv  = (float)(word & 524287u) * (1.0f / DT_SCALE);
        float2   r    = rate2[(loc >> 1) & (F - 1)];
        float v0 = __expf(-r.x * dtv);
        float v1 = __expf(-r.y * dtv);
        atomicAdd(&acc[loc >> 1], __floats2half2_rn(v0, v1));
    }
    __syncthreads();

    long long base_f = (long long)bin * (SEGS_PER_BIN * ROW);
    long long nf     = n_out * ROW - base_f;
    if (nf <= 0) return;
    if (nf > SEGS_PER_BIN * ROW) nf = SEGS_PER_BIN * ROW;
    int nf4 = (int)(nf >> 2);                           // float4 count (<=2048)
    float4* dst = (float4*)(out + base_f);
    for (int j = t; j < nf4; j += 512) {
        float2 a = __half22float2(acc[2 * j]);
        float2 b = __half22float2(acc[2 * j + 1]);
        __stcs(&dst[j], make_float4(a.x, a.y, b.x, b.y));
    }
}

// ---------------------------------------------------------------------------
// metadata order: 0=dt[E] f32, 1=times_out (unused), 2=decay_rate[256] f32,
//                 3=successor_kernel_channel_ids[E] i32, 4=segment_ids_out[E] i32
// output: f32[n_out*1024]
// ---------------------------------------------------------------------------
extern "C" void kernel_launch(void* const* d_in, const int* in_sizes, int n_in,
                              void* d_out, int out_size) {
    const float* dt    = (const float*)d_in[0];
    const float* decay = (const float*)d_in[2];
    const int*   ids   = (const int*)d_in[3];
    const int*   segs  = (const int*)d_in[4];
    float*       out   = (float*)d_out;

    int E  = in_sizes[0];
    int n4 = E >> 2;
    long long n_out = (long long)out_size / ROW;

    int chunk = (n4 + NBLK - 1) / NBLK;

    count_kernel<<<NBLK, 1024>>>((const int4*)segs, n4, segs, E, chunk);
    scan_blocks_kernel<<<NBINS / 256, 256>>>();
    base_scan_kernel<<<1, 1024>>>();
    // place grid must match count grid (same chunk decomposition)
    place_kernel<<<NBLK, 1024>>>(
        (const float4*)dt, (const int4*)ids, (const int4*)segs,
        n4, dt, ids, segs, E, chunk);

    long long bins_rt = (n_out + SEGS_PER_BIN - 1) / SEGS_PER_BIN;
    if (bins_rt > NBINS) bins_rt = NBINS;
    gather_kernel<<<(unsigned)bins_rt, 512>>>(decay, out, n_out);
}

// round 17
// speedup vs baseline: 1.2712x; 1.2712x over previous
#include <cuda_runtime.h>
#include <cuda_fp16.h>
#include <cstdint>

#define F 128
#define M 2
#define ROW 1024                 // STRIDE*F*M floats per output row
#define SEGS_PER_BIN 8           // 8 rows; tile = 4096 half2 = 16KB; bin = seg >> 3
#define NBINS 8192               // covers 65536 segments
#define NBLK 148                 // one count/place block per SM
#define EMAX 4200448             // max events (E=4194304 + slack)
#define DT_SCALE 524287.0f       // 2^19 - 1

// Static scratch. g_sorted packed 4B/event: 16.8MB -> L2-resident after place.
__device__ unsigned g_sorted[EMAX];
__device__ unsigned g_counts[(size_t)NBLK * NBINS];
__device__ unsigned g_offs[(size_t)NBLK * NBINS];
__device__ unsigned g_totals[NBINS];
__device__ unsigned g_base[NBINS];

// ---------------------------------------------------------------------------
// Pass 1: per-block histogram of bins (smem atomics only), coalesced dump.
// 2x ILP; reads ONLY the segment array (16MB).
// ---------------------------------------------------------------------------
__global__ void __launch_bounds__(1024) count_kernel(
    const int4* __restrict__ seg4, int n4,
    const int*  __restrict__ seg_s, int n_events, int chunk)
{
    __shared__ unsigned cnt[NBINS];   // 32KB
    int t = threadIdx.x;
    for (int i = t; i < NBINS; i += 1024) cnt[i] = 0;
    __syncthreads();

    int start = blockIdx.x * chunk;
    int end   = start + chunk; if (end > n4) end = n4;
    for (int i = start + t; i < end; i += 2048) {
        int4 a = __ldcs(&seg4[i]);
        int  j = i + 1024;
        bool hb = j < end;
        int4 b;
        if (hb) b = __ldcs(&seg4[j]);
        atomicAdd(&cnt[(unsigned)a.x >> 3], 1u);
        atomicAdd(&cnt[(unsigned)a.y >> 3], 1u);
        atomicAdd(&cnt[(unsigned)a.z >> 3], 1u);
        atomicAdd(&cnt[(unsigned)a.w >> 3], 1u);
        if (hb) {
            atomicAdd(&cnt[(unsigned)b.x >> 3], 1u);
            atomicAdd(&cnt[(unsigned)b.y >> 3], 1u);
            atomicAdd(&cnt[(unsigned)b.z >> 3], 1u);
            atomicAdd(&cnt[(unsigned)b.w >> 3], 1u);
        }
    }
    int rem = n_events & 3;
    if (blockIdx.x == 0 && t < rem)
        atomicAdd(&cnt[(unsigned)seg_s[n4 * 4 + t] >> 3], 1u);
    __syncthreads();

    unsigned* dst = g_counts + (size_t)blockIdx.x * NBINS;
    for (int i = t; i < NBINS; i += 1024) dst[i] = cnt[i];
}

// ---------------------------------------------------------------------------
// Pass 2a: per-bin serial scan across blocks (coalesced across lanes).
// ---------------------------------------------------------------------------
__global__ void scan_blocks_kernel() {
    int i = blockIdx.x * blockDim.x + threadIdx.x;
    if (i >= NBINS) return;
    unsigned run = 0;
    #pragma unroll 4
    for (int b = 0; b < NBLK; b++) {
        unsigned c = g_counts[(size_t)b * NBINS + i];
        g_offs[(size_t)b * NBINS + i] = run;
        run += c;
    }
    g_totals[i] = run;
}

// ---------------------------------------------------------------------------
// Pass 2b: exclusive scan of the 8192 bin totals (single block).
// ---------------------------------------------------------------------------
__global__ void __launch_bounds__(1024) base_scan_kernel() {
    __shared__ unsigned s[1024];
    int t = threadIdx.x;
    unsigned loc[8], v = 0;
    #pragma unroll
    for (int j = 0; j < 8; j++) { loc[j] = g_totals[t * 8 + j]; v += loc[j]; }
    s[t] = v;
    __syncthreads();
    for (int off = 1; off < 1024; off <<= 1) {
        unsigned x = (t >= off) ? s[t - off] : 0u;
        __syncthreads();
        s[t] += x;
        __syncthreads();
    }
    unsigned run = s[t] - v;   // exclusive prefix
    #pragma unroll
    for (int j = 0; j < 8; j++) { g_base[t * 8 + j] = run; run += loc[j]; }
}

// ---------------------------------------------------------------------------
// Pass 3: single full-range place (4-event body; measured floor ~37us).
// Events packed to 4B (loc13 | dt19); positions via smem atomicAdd.
// ---------------------------------------------------------------------------
__global__ void __launch_bounds__(1024) place_kernel(
    const float4* __restrict__ dt4,
    const int4*   __restrict__ id4,
    const int4*   __restrict__ seg4,
    int n4,
    const float* __restrict__ dt_s,
    const int*   __restrict__ id_s,
    const int*   __restrict__ seg_s,
    int n_events, int chunk)
{
    __shared__ unsigned s_off[NBINS];   // 32KB
    int t = threadIdx.x;
    const unsigned* offs = g_offs + (size_t)blockIdx.x * NBINS;
    for (int i = t; i < NBINS; i += 1024) s_off[i] = g_base[i] + offs[i];
    __syncthreads();

    int start = blockIdx.x * chunk;
    int end   = start + chunk; if (end > n4) end = n4;
    for (int i = start + t; i < end; i += 1024) {
        float4 d  = __ldcs(&dt4[i]);
        int4   id = __ldcs(&id4[i]);
        int4   sg = __ldcs(&seg4[i]);
        float dts[4] = {d.x, d.y, d.z, d.w};
        int   ids[4] = {id.x, id.y, id.z, id.w};
        int   sgs[4] = {sg.x, sg.y, sg.z, sg.w};
        #pragma unroll
        for (int k = 0; k < 4; k++) {
            unsigned bin = (unsigned)sgs[k] >> 3;
            unsigned pos = atomicAdd(&s_off[bin], 1u);
            unsigned lc  = (((unsigned)sgs[k] & 7u) << 10) | ((unsigned)ids[k] << 1);
            float dq = fminf(fmaxf(dts[k], 0.f), 1.f);
            unsigned q = (unsigned)__fmaf_rn(dq, DT_SCALE, 0.5f);
            if (q > 524287u) q = 524287u;
            g_sorted[pos] = (lc << 19) | q;
        }
    }
    int rem = n_events & 3;
    if (blockIdx.x == 0 && t < rem) {
        int e = n4 * 4 + t;
        unsigned bin = (unsigned)seg_s[e] >> 3;
        unsigned pos = atomicAdd(&s_off[bin], 1u);
        unsigned lc  = (((unsigned)seg_s[e] & 7u) << 10) | ((unsigned)id_s[e] << 1);
        float dq = fminf(fmaxf(dt_s[e], 0.f), 1.f);
        unsigned q = (unsigned)__fmaf_rn(dq, DT_SCALE, 0.5f);
        if (q > 524287u) q = 524287u;
        g_sorted[pos] = (lc << 19) | q;
    }
}

// ---------------------------------------------------------------------------
// Pass 4: one 256-thread block per bin. PREFETCH the bin's events into
// registers (up to 4/thread, covers cnt<=1024; Poisson(512) overflow ~never)
// concurrently with the tile zeroing, so the L2 load latency is hidden.
// Accumulate in a 16KB half2 tile (one smem atomic per event), stream the
// tile out as fp32 with evict-first float4 stores.
// ---------------------------------------------------------------------------
__device__ __forceinline__ void gev(unsigned word, const float2* rate2,
                                    __half2* acc) {
    unsigned loc = word >> 19;
    float    dtv = (float)(word & 524287u) * (1.0f / DT_SCALE);
    float2   r   = rate2[(loc >> 1) & (F - 1)];
    float v0 = __expf(-r.x * dtv);
    float v1 = __expf(-r.y * dtv);
    atomicAdd(&acc[loc >> 1], __floats2half2_rn(v0, v1));
}

__global__ void __launch_bounds__(256) gather_kernel(
    const float* __restrict__ decay,   // [F*M]
    float* __restrict__ out,
    long long n_out)
{
    __shared__ __half2 acc[SEGS_PER_BIN * ROW / 2];   // 16KB; index = loc>>1
    __shared__ float2  rate2[F];

    int t = threadIdx.x;
    unsigned bin   = blockIdx.x;
    unsigned start = g_base[bin];
    unsigned cnt   = g_totals[bin];
    unsigned end   = start + cnt;

    // issue event prefetch loads FIRST (independent of smem)
    unsigned e0 = start + t, e1 = e0 + 256, e2 = e1 + 256, e3 = e2 + 256;
    bool v0 = e0 < end, v1 = e1 < end, v2 = e2 < end, v3 = e3 < end;
    unsigned w0 = 0, w1 = 0, w2 = 0, w3 = 0;
    if (v0) w0 = g_sorted[e0];
    if (v1) w1 = g_sorted[e1];
    if (v2) w2 = g_sorted[e2];
    if (v3) w3 = g_sorted[e3];

    // zero tile + build rate table while loads are in flight
    uint2* accz = (uint2*)acc;                         // 2048 x 8B
    #pragma unroll
    for (int j = 0; j < 2048 / 256; j++)
        accz[j * 256 + t] = make_uint2(0u, 0u);
    if (t < F) {
        float x0 = decay[t * M + 0];
        float x1 = decay[t * M + 1];
        rate2[t].x = fmaxf(x0, 0.f) + log1pf(expf(-fabsf(x0)));
        rate2[t].y = fmaxf(x1, 0.f) + log1pf(expf(-fabsf(x1)));
    }
    __syncthreads();

    if (v0) gev(w0, rate2, acc);
    if (v1) gev(w1, rate2, acc);
    if (v2) gev(w2, rate2, acc);
    if (v3) gev(w3, rate2, acc);
    // overflow (cnt > 1024): rare
    for (unsigned e = start + t + 1024; e < end; e += 256)
        gev(g_sorted[e], rate2, acc);
    __syncthreads();

    long long base_f = (long long)bin * (SEGS_PER_BIN * ROW);
    long long nf     = n_out * ROW - base_f;
    if (nf <= 0) return;
    if (nf > SEGS_PER_BIN * ROW) nf = SEGS_PER_BIN * ROW;
    int nf4 = (int)(nf >> 2);                           // float4 count (<=2048)
    float4* dst = (float4*)(out + base_f);
    for (int j = t; j < nf4; j += 256) {
        float2 a = __half22float2(acc[2 * j]);
        float2 b = __half22float2(acc[2 * j + 1]);
        __stcs(&dst[j], make_float4(a.x, a.y, b.x, b.y));
    }
}

// ---------------------------------------------------------------------------
// metadata order: 0=dt[E] f32, 1=times_out (unused), 2=decay_rate[256] f32,
//                 3=successor_kernel_channel_ids[E] i32, 4=segment_ids_out[E] i32
// output: f32[n_out*1024]
// ---------------------------------------------------------------------------
extern "C" void kernel_launch(void* const* d_in, const int* in_sizes, int n_in,
                              void* d_out, int out_size) {
    const float* dt    = (const float*)d_in[0];
    const float* decay = (const float*)d_in[2];
    const int*   ids   = (const int*)d_in[3];
    const int*   segs  = (const int*)d_in[4];
    float*       out   = (float*)d_out;

    int E  = in_sizes[0];
    int n4 = E >> 2;
    long long n_out = (long long)out_size / ROW;

    int chunk = (n4 + NBLK - 1) / NBLK;

    count_kernel<<<NBLK, 1024>>>((const int4*)segs, n4, segs, E, chunk);
    scan_blocks_kernel<<<NBINS / 256, 256>>>();
    base_scan_kernel<<<1, 1024>>>();
    place_kernel<<<NBLK, 1024>>>(
        (const float4*)dt, (const int4*)ids, (const int4*)segs,
        n4, dt, ids, segs, E, chunk);

    long long bins_rt = (n_out + SEGS_PER_BIN - 1) / SEGS_PER_BIN;
    if (bins_rt > NBINS) bins_rt = NBINS;
    gather_kernel<<<(unsigned)bins_rt, 256>>>(decay, out, n_out);
}